// round 4
// baseline (speedup 1.0000x reference)
#include <cuda_runtime.h>
#include <mma.h>
#include <math.h>
#include <stdint.h>

using namespace nvcuda;

#define BB 8
#define NN 20000
#define EE 40000
#define HH 128
#define TT 64
#define LL 4

__device__ __forceinline__ uint32_t f2tf(float f) {
    uint32_t u;
    asm("cvt.rna.tf32.f32 %0, %1;" : "=r"(u) : "f"(f));
    return u;
}
__device__ __forceinline__ float silu_f(float v) { return v / (1.f + __expf(-v)); }

// ---------------- scratch (static device globals) --------------------------
__device__ float g_temb[BB * HH];
__device__ float g_table4[4 * HH];
__device__ float g_h[BB * NN * HH];
__device__ float g_agg[BB * NN * HH];
__device__ float g_x[BB * NN * 3];
__device__ float g_cupd[BB * NN * 3];
__device__ float g_dist[BB * EE];
__device__ float g_cdn[BB * EE * 3];
__device__ float g_m[BB * EE * HH];
__device__ int   g_deg[NN];
__device__ int   g_off[NN + 1];
__device__ int   g_cur[NN];
__device__ int   g_csr[2 * EE];

// ---------------- shared wmma helpers --------------------------------------
#define LDT 136   // chained-tile leading dim (floats)
#define LDA 36    // stage-1 A tile leading dim

using FragC = wmma::fragment<wmma::accumulator, 16, 16, 8, float>;
using FragA = wmma::fragment<wmma::matrix_a, 16, 16, 8, wmma::precision::tf32, wmma::row_major>;
using FragB = wmma::fragment<wmma::matrix_b, 16, 16, 8, wmma::precision::tf32, wmma::row_major>;

// load 32 k-rows x 128 cols of W (K-major), tf32-round, into Bs[32][LDT]
__device__ __forceinline__ void stage_B(float* Bs, const float* __restrict__ W,
                                        int k0, int tid)
{
    const int bkrow = tid >> 3;
    const int bnc   = (tid & 7) * 16;
    const float* wbase = W + (long)(k0 + bkrow) * 128 + bnc;
#pragma unroll
    for (int q = 0; q < 4; q++) {
        float4 v = *(const float4*)(wbase + q * 4);
        uint4 bv;
        bv.x = f2tf(v.x); bv.y = f2tf(v.y); bv.z = f2tf(v.z); bv.w = f2tf(v.w);
        *(uint4*)(Bs + bkrow * LDT + bnc + q * 4) = bv;
    }
}

// one 32-K chunk of MMA: A tile (lda) x Bs[32][LDT] -> c[2][4]
__device__ __forceinline__ void mma_chunk(FragC c[2][4], const float* Asrc, int lda,
                                          const float* Bs, int wm, int wn)
{
#pragma unroll
    for (int kk = 0; kk < 32; kk += 8) {
        FragA a[2];
        FragB b[4];
#pragma unroll
        for (int i = 0; i < 2; i++)
            wmma::load_matrix_sync(a[i], Asrc + (wm * 32 + i * 16) * lda + kk, lda);
#pragma unroll
        for (int j = 0; j < 4; j++)
            wmma::load_matrix_sync(b[j], Bs + kk * LDT + wn * 64 + j * 16, LDT);
#pragma unroll
        for (int i = 0; i < 2; i++)
#pragma unroll
            for (int j = 0; j < 4; j++)
                wmma::mma_sync(c[i][j], a[i], b[j], c[i][j]);
    }
}

__device__ __forceinline__ void zero_c(FragC c[2][4])
{
#pragma unroll
    for (int i = 0; i < 2; i++)
#pragma unroll
        for (int j = 0; j < 4; j++) wmma::fill_fragment(c[i][j], 0.f);
}

__device__ __forceinline__ void store_c(FragC c[2][4], float* T, int wm, int wn)
{
#pragma unroll
    for (int i = 0; i < 2; i++)
#pragma unroll
        for (int j = 0; j < 4; j++)
            wmma::store_matrix_sync(T + (wm * 32 + i * 16) * LDT + wn * 64 + j * 16,
                                    c[i][j], LDT, wmma::mem_row_major);
}

// ---------------- fused edge kernel ----------------------------------------
// m1 = silu([h_src|h_dst]@Wm1 + dist*w256 + bm1)   (K=256, gathered A)
// m  = silu(m1@Wm2 + bm2)            -> g_m (global) and smem
// c1 = silu(m@Wc1 + bc1); cw = c1.Wc2 ; coord atomics
// dyn smem floats: M1s[128*LDT] | M2s[128*LDT] | As[128*LDA] | Bs[32*LDT]
#define EDGE_SMEM ((2 * 128 * LDT + 128 * LDA + 32 * LDT) * 4)   // 175104 B

__global__ void __launch_bounds__(256)
edge_fused_k(const float* __restrict__ Wm1, const float* __restrict__ bm1,
             const float* __restrict__ w256,
             const float* __restrict__ Wm2, const float* __restrict__ bm2,
             const float* __restrict__ Wc1, const float* __restrict__ bc1,
             const float* __restrict__ Wc2, const int* __restrict__ bonds)
{
    extern __shared__ float dyn[];
    float* M1s = dyn;
    float* M2s = dyn + 128 * LDT;
    float* As  = dyn + 2 * 128 * LDT;
    float* Bs  = dyn + 2 * 128 * LDT + 128 * LDA;

    __shared__ float b1s[128], b2s[128], bc1s[128], wc2s[128], wds[128];
    __shared__ const float* pA0[128];
    __shared__ const float* pA1[128];

    const int tid = threadIdx.x;
    const int wid = tid >> 5;
    const int wm = wid & 3, wn = wid >> 2;
    const long row0 = (long)blockIdx.x * 128;

    if (tid < 128) {
        b1s[tid] = bm1[tid]; b2s[tid] = bm2[tid];
        bc1s[tid] = bc1[tid]; wc2s[tid] = Wc2[tid]; wds[tid] = w256[tid];
        long gr = row0 + tid;
        int b = (int)(gr / EE), e = (int)(gr - (long)b * EE);
        int s = bonds[2 * e], d = bonds[2 * e + 1];
        pA0[tid] = g_h + ((long)b * NN + s) * HH;
        pA1[tid] = g_h + ((long)b * NN + d) * HH;
    }
    __syncthreads();

    FragC c[2][4];
    zero_c(c);
    const int arow = tid >> 1;
    const int akb  = (tid & 1) * 16;

    // ---- stage 1: K=256 gather GEMM ----
    for (int k0 = 0; k0 < 256; k0 += 32) {
        const float* abase = ((k0 < 128) ? pA0[arow] : pA1[arow]) + (k0 & 127) + akb;
#pragma unroll
        for (int q = 0; q < 4; q++) {
            float4 v = *(const float4*)(abase + q * 4);
            uint4 av;
            av.x = f2tf(v.x); av.y = f2tf(v.y); av.z = f2tf(v.z); av.w = f2tf(v.w);
            *(uint4*)(As + arow * LDA + akb + q * 4) = av;
        }
        stage_B(Bs, Wm1, k0, tid);
        __syncthreads();
        mma_chunk(c, As, LDA, Bs, wm, wn);
        __syncthreads();
    }
    store_c(c, M1s, wm, wn);
    __syncthreads();
    {   // elementwise: silu(+bias+dist term), tf32-round in place
        const int row = tid >> 1, cb = (tid & 1) * 64;
        const float dv = g_dist[row0 + row];
        float* p = M1s + row * LDT + cb;
#pragma unroll
        for (int j = 0; j < 64; j++) {
            float v = silu_f(p[j] + b1s[cb + j] + dv * wds[cb + j]);
            ((uint32_t*)p)[j] = f2tf(v);
        }
    }
    __syncthreads();

    // ---- stage 2: m = silu(m1@Wm2+b) ----
    zero_c(c);
    for (int k0 = 0; k0 < 128; k0 += 32) {
        stage_B(Bs, Wm2, k0, tid);
        __syncthreads();
        mma_chunk(c, M1s + k0, LDT, Bs, wm, wn);
        __syncthreads();
    }
    store_c(c, M2s, wm, wn);
    __syncthreads();
    {   // elementwise: silu, write g_m (fp32), tf32 in smem
        const int row = tid >> 1, cb = (tid & 1) * 64;
        const long gr = row0 + row;
        float* p = M2s + row * LDT + cb;
        float* gm = g_m + gr * HH + cb;
#pragma unroll
        for (int j = 0; j < 64; j += 4) {
            float4 o;
            o.x = silu_f(p[j + 0] + b2s[cb + j + 0]);
            o.y = silu_f(p[j + 1] + b2s[cb + j + 1]);
            o.z = silu_f(p[j + 2] + b2s[cb + j + 2]);
            o.w = silu_f(p[j + 3] + b2s[cb + j + 3]);
            *(float4*)(gm + j) = o;
            ((uint32_t*)p)[j + 0] = f2tf(o.x);
            ((uint32_t*)p)[j + 1] = f2tf(o.y);
            ((uint32_t*)p)[j + 2] = f2tf(o.z);
            ((uint32_t*)p)[j + 3] = f2tf(o.w);
        }
    }
    __syncthreads();

    // ---- stage 3: c1 = silu(m@Wc1+b); cw = c1.Wc2; coord atomics ----
    zero_c(c);
    for (int k0 = 0; k0 < 128; k0 += 32) {
        stage_B(Bs, Wc1, k0, tid);
        __syncthreads();
        mma_chunk(c, M2s + k0, LDT, Bs, wm, wn);
        __syncthreads();
    }
    store_c(c, M1s, wm, wn);
    __syncthreads();
    if (tid < 128) {
        const float* crow = M1s + tid * LDT;
        float cw = 0.f;
#pragma unroll 16
        for (int col = 0; col < 128; col++)
            cw += silu_f(crow[col] + bc1s[col]) * wc2s[col];
        long gr = row0 + tid;
        int b = (int)(gr / EE), e = (int)(gr - (long)b * EE);
        int s = bonds[2 * e], d = bonds[2 * e + 1];
        const float* cd = g_cdn + gr * 3;
#pragma unroll
        for (int cc = 0; cc < 3; cc++) {
            float u = cd[cc] * cw;
            atomicAdd(&g_cupd[((long)b * NN + d) * 3 + cc], u);
            atomicAdd(&g_cupd[((long)b * NN + s) * 3 + cc], -u);
        }
    }
}

// ---------------- fused node kernel ----------------------------------------
// n1 = silu([h|agg]@Wn1 + bn1) (K=256); h = h + n1@Wn2 + bn2
// dyn smem floats: N1s[128*LDT] | As[128*LDA] | Bs[32*LDT]   (105472 B -> 2 CTA/SM)
#define NODE_SMEM ((128 * LDT + 128 * LDA + 32 * LDT) * 4)

__global__ void __launch_bounds__(256)
node_fused_k(const float* __restrict__ Wn1, const float* __restrict__ bn1,
             const float* __restrict__ Wn2, const float* __restrict__ bn2)
{
    extern __shared__ float dyn[];
    float* N1s = dyn;
    float* As  = dyn + 128 * LDT;
    float* Bs  = dyn + 128 * LDT + 128 * LDA;

    __shared__ float b1s[128], b2s[128];

    const int tid = threadIdx.x;
    const int wid = tid >> 5;
    const int wm = wid & 3, wn = wid >> 2;
    const long row0 = (long)blockIdx.x * 128;

    if (tid < 128) { b1s[tid] = bn1[tid]; b2s[tid] = bn2[tid]; }
    __syncthreads();

    FragC c[2][4];
    zero_c(c);
    const int arow = tid >> 1;
    const int akb  = (tid & 1) * 16;

    for (int k0 = 0; k0 < 256; k0 += 32) {
        const long gr = row0 + arow;
        const float* abase = ((k0 < 128) ? (g_h + gr * HH) : (g_agg + gr * HH)) + (k0 & 127) + akb;
#pragma unroll
        for (int q = 0; q < 4; q++) {
            float4 v = *(const float4*)(abase + q * 4);
            uint4 av;
            av.x = f2tf(v.x); av.y = f2tf(v.y); av.z = f2tf(v.z); av.w = f2tf(v.w);
            *(uint4*)(As + arow * LDA + akb + q * 4) = av;
        }
        stage_B(Bs, Wn1, k0, tid);
        __syncthreads();
        mma_chunk(c, As, LDA, Bs, wm, wn);
        __syncthreads();
    }
    store_c(c, N1s, wm, wn);
    __syncthreads();
    {
        const int row = tid >> 1, cb = (tid & 1) * 64;
        float* p = N1s + row * LDT + cb;
#pragma unroll
        for (int j = 0; j < 64; j++)
            ((uint32_t*)p)[j] = f2tf(silu_f(p[j] + b1s[cb + j]));
    }
    __syncthreads();

    zero_c(c);
    for (int k0 = 0; k0 < 128; k0 += 32) {
        stage_B(Bs, Wn2, k0, tid);
        __syncthreads();
        mma_chunk(c, N1s + k0, LDT, Bs, wm, wn);
        __syncthreads();
    }
    // epilogue: h += acc + b2 — write straight from a staging pass via smem reuse
    store_c(c, N1s, wm, wn);
    __syncthreads();
    {
        const int row = tid >> 1, cb = (tid & 1) * 64;
        const long gr = row0 + row;
        const float* p = N1s + row * LDT + cb;
        float* hp = g_h + gr * HH + cb;
#pragma unroll
        for (int j = 0; j < 64; j += 4) {
            float4 hv = *(const float4*)(hp + j);
            float4 o;
            o.x = hv.x + p[j + 0] + b2s[cb + j + 0];
            o.y = hv.y + p[j + 1] + b2s[cb + j + 1];
            o.z = hv.z + p[j + 2] + b2s[cb + j + 2];
            o.w = hv.w + p[j + 3] + b2s[cb + j + 3];
            *(float4*)(hp + j) = o;
        }
    }
}

// ---------------- fused output kernel --------------------------------------
// o1 = silu(h@Wo1 + bo1); out = o1@Wo2 + bo2 + (x_final - x_in)
#define OUT_SMEM ((128 * LDT + 128 * LDA + 32 * LDT) * 4)

__global__ void __launch_bounds__(256)
out_fused_k(const float* __restrict__ Wo1, const float* __restrict__ bo1,
            const float* __restrict__ Wo2, const float* __restrict__ bo2,
            const float* __restrict__ x_in, float* __restrict__ out)
{
    extern __shared__ float dyn[];
    float* O1s = dyn;
    float* As  = dyn + 128 * LDT;
    float* Bs  = dyn + 128 * LDT + 128 * LDA;

    __shared__ float b1s[128];
    __shared__ float wo2s[128 * 3];

    const int tid = threadIdx.x;
    const int wid = tid >> 5;
    const int wm = wid & 3, wn = wid >> 2;
    const long row0 = (long)blockIdx.x * 128;

    if (tid < 128) b1s[tid] = bo1[tid];
    for (int i = tid; i < 384; i += 256) wo2s[i] = Wo2[i];
    __syncthreads();

    FragC c[2][4];
    zero_c(c);
    const int arow = tid >> 1;
    const int akb  = (tid & 1) * 16;

    for (int k0 = 0; k0 < 128; k0 += 32) {
        const float* abase = g_h + (row0 + arow) * (long)HH + k0 + akb;
#pragma unroll
        for (int q = 0; q < 4; q++) {
            float4 v = *(const float4*)(abase + q * 4);
            uint4 av;
            av.x = f2tf(v.x); av.y = f2tf(v.y); av.z = f2tf(v.z); av.w = f2tf(v.w);
            *(uint4*)(As + arow * LDA + akb + q * 4) = av;
        }
        stage_B(Bs, Wo1, k0, tid);
        __syncthreads();
        mma_chunk(c, As, LDA, Bs, wm, wn);
        __syncthreads();
    }
    store_c(c, O1s, wm, wn);
    __syncthreads();
    if (tid < 128) {
        const float* crow = O1s + tid * LDT;
        float a0 = 0.f, a1 = 0.f, a2 = 0.f;
#pragma unroll 16
        for (int col = 0; col < 128; col++) {
            float v = silu_f(crow[col] + b1s[col]);
            a0 += v * wo2s[col * 3 + 0];
            a1 += v * wo2s[col * 3 + 1];
            a2 += v * wo2s[col * 3 + 2];
        }
        long gr = row0 + tid;
        long base = gr * 3;
        out[base + 0] = a0 + bo2[0] + g_x[base + 0] - x_in[base + 0];
        out[base + 1] = a1 + bo2[1] + g_x[base + 1] - x_in[base + 1];
        out[base + 2] = a2 + bo2[2] + g_x[base + 2] - x_in[base + 2];
    }
}

// ---------------- small kernels -------------------------------------------
__global__ void time_embed_k(const float* __restrict__ t,
                             const float* __restrict__ W1, const float* __restrict__ b1,
                             const float* __restrict__ W2, const float* __restrict__ b2)
{
    __shared__ float te[BB][TT];
    __shared__ float s1[BB][HH];
    int tid = threadIdx.x;
    const int half = TT / 2;
    for (int idx = tid; idx < BB * TT; idx += 128) {
        int b = idx / TT, k = idx % TT;
        int kk = (k < half) ? k : (k - half);
        float f = __expf((float)kk * (-logf(10000.f) / (float)(half - 1)));
        float a = t[b] * f;
        te[b][k] = (k < half) ? sinf(a) : cosf(a);
    }
    __syncthreads();
    for (int b = 0; b < BB; b++) {
        float acc = b1[tid];
        for (int k = 0; k < TT; k++) acc += te[b][k] * W1[k * HH + tid];
        s1[b][tid] = silu_f(acc);
    }
    __syncthreads();
    for (int b = 0; b < BB; b++) {
        float acc = b2[tid];
        for (int k = 0; k < HH; k++) acc += s1[b][k] * W2[k * HH + tid];
        g_temb[b * HH + tid] = acc;
    }
}

__global__ void table4_k(const float* __restrict__ emb,
                         const float* __restrict__ Wn, const float* __restrict__ bn)
{
    int a = blockIdx.x, j = threadIdx.x;
    float acc = bn[j];
    for (int k = 0; k < HH; k++) acc += emb[a * HH + k] * Wn[k * HH + j];
    g_table4[a * HH + j] = acc;
}

__global__ void h_init_k(const int* __restrict__ types)
{
    long idx = (long)blockIdx.x * 256 + threadIdx.x;
    if (idx >= (long)BB * NN * HH) return;
    int j = (int)(idx & 127);
    long bn = idx >> 7;
    int n = (int)(bn % NN), b = (int)(bn / NN);
    g_h[idx] = g_table4[types[n] * HH + j] + g_temb[b * HH + j];
}

__global__ void init_x_k(const float* __restrict__ x)
{
    int idx = blockIdx.x * 256 + threadIdx.x;
    if (idx < BB * NN * 3) g_x[idx] = x[idx];
}

__global__ void zero_f_k(float* __restrict__ p, long n)
{
    long idx = (long)blockIdx.x * 256 + threadIdx.x;
    if (idx < n) p[idx] = 0.f;
}
__global__ void zero_i_k(int* __restrict__ p, int n)
{
    int idx = blockIdx.x * 256 + threadIdx.x;
    if (idx < n) p[idx] = 0;
}

__global__ void deg_count_k(const int* __restrict__ bonds)
{
    int e = blockIdx.x * 256 + threadIdx.x;
    if (e >= EE) return;
    atomicAdd(&g_deg[bonds[2 * e]], 1);
    atomicAdd(&g_deg[bonds[2 * e + 1]], 1);
}

__global__ void scan_k()
{
    __shared__ int sh[256];
    __shared__ int base;
    int tid = threadIdx.x;
    if (tid == 0) base = 0;
    __syncthreads();
    for (int i0 = 0; i0 < NN; i0 += 256) {
        int i = i0 + tid;
        int v = (i < NN) ? g_deg[i] : 0;
        sh[tid] = v;
        __syncthreads();
        for (int o = 1; o < 256; o <<= 1) {
            int t = (tid >= o) ? sh[tid - o] : 0;
            __syncthreads();
            sh[tid] += t;
            __syncthreads();
        }
        int excl = base + sh[tid] - v;
        if (i < NN) { g_off[i] = excl; g_cur[i] = excl; }
        __syncthreads();
        if (tid == 255) base += sh[255];
        __syncthreads();
    }
    if (tid == 0) g_off[NN] = base;
}

__global__ void fill_k(const int* __restrict__ bonds)
{
    int e = blockIdx.x * 256 + threadIdx.x;
    if (e >= EE) return;
    int s = bonds[2 * e], d = bonds[2 * e + 1];
    int p = atomicAdd(&g_cur[s], 1); g_csr[p] = e;
    int q = atomicAdd(&g_cur[d], 1); g_csr[q] = e;
}

__global__ void edge_geom_k(const int* __restrict__ bonds)
{
    int idx = blockIdx.x * 256 + threadIdx.x;
    if (idx >= BB * EE) return;
    int b = idx / EE, e = idx - b * EE;
    int s = bonds[2 * e], d = bonds[2 * e + 1];
    const float* xs = g_x + ((long)b * NN + s) * 3;
    const float* xd = g_x + ((long)b * NN + d) * 3;
    float dx = xd[0] - xs[0], dy = xd[1] - xs[1], dz = xd[2] - xs[2];
    float dist = sqrtf(dx * dx + dy * dy + dz * dz);
    g_dist[idx] = dist;
    float inv = 1.f / (dist + 1e-8f);
    g_cdn[idx * 3 + 0] = dx * inv;
    g_cdn[idx * 3 + 1] = dy * inv;
    g_cdn[idx * 3 + 2] = dz * inv;
}

// agg[b,n,:] = sum over incident edges of m[b,e,:] (CSR gather, no atomics)
__global__ void agg_gather_k()
{
    int warp = (blockIdx.x * 256 + threadIdx.x) >> 5;
    int lane = threadIdx.x & 31;
    if (warp >= BB * NN) return;
    int b = warp / NN, n = warp - b * NN;
    int o0 = g_off[n], o1 = g_off[n + 1];
    float4 acc = make_float4(0.f, 0.f, 0.f, 0.f);
    for (int j = o0; j < o1; j++) {
        int e = g_csr[j];
        float4 v = ((const float4*)(g_m + ((long)b * EE + e) * HH))[lane];
        acc.x += v.x; acc.y += v.y; acc.z += v.z; acc.w += v.w;
    }
    ((float4*)(g_agg + (long)warp * HH))[lane] = acc;
}

__global__ void x_update_k()
{
    int idx = blockIdx.x * 256 + threadIdx.x;
    if (idx >= BB * NN * 3) return;
    int n = (idx / 3) % NN;
    g_x[idx] += g_cupd[idx] / fmaxf((float)g_deg[n], 1.f);
}

// ---------------- launch ---------------------------------------------------
static inline int cdiv(long n, int b) { return (int)((n + b - 1) / b); }

extern "C" void kernel_launch(void* const* d_in, const int* in_sizes, int n_in,
                              void* d_out, int out_size)
{
    const float* x      = (const float*)d_in[0];
    const float* t      = (const float*)d_in[1];
    const int*   types  = (const int*)d_in[2];
    const int*   bonds  = (const int*)d_in[3];
    const float* emb    = (const float*)d_in[4];
    const float* W_t1   = (const float*)d_in[5];
    const float* b_t1   = (const float*)d_in[6];
    const float* W_t2   = (const float*)d_in[7];
    const float* b_t2   = (const float*)d_in[8];
    const float* W_node = (const float*)d_in[9];
    const float* b_node = (const float*)d_in[10];
    const float* Wm1    = (const float*)d_in[11];
    const float* bm1    = (const float*)d_in[12];
    const float* Wm2    = (const float*)d_in[13];
    const float* bm2    = (const float*)d_in[14];
    const float* Wn1    = (const float*)d_in[15];
    const float* bn1    = (const float*)d_in[16];
    const float* Wn2    = (const float*)d_in[17];
    const float* bn2    = (const float*)d_in[18];
    const float* Wc1    = (const float*)d_in[19];
    const float* bc1    = (const float*)d_in[20];
    const float* Wc2    = (const float*)d_in[21];
    const float* Wo1    = (const float*)d_in[22];
    const float* bo1    = (const float*)d_in[23];
    const float* Wo2    = (const float*)d_in[24];
    const float* bo2    = (const float*)d_in[25];
    float* out = (float*)d_out;

    float *p_cupd;
    int *p_deg;
    cudaGetSymbolAddress((void**)&p_cupd, g_cupd);
    cudaGetSymbolAddress((void**)&p_deg, g_deg);

    cudaFuncSetAttribute(edge_fused_k, cudaFuncAttributeMaxDynamicSharedMemorySize, EDGE_SMEM);
    cudaFuncSetAttribute(node_fused_k, cudaFuncAttributeMaxDynamicSharedMemorySize, NODE_SMEM);
    cudaFuncSetAttribute(out_fused_k, cudaFuncAttributeMaxDynamicSharedMemorySize, OUT_SMEM);

    // embeddings, init, CSR
    time_embed_k<<<1, 128>>>(t, W_t1, b_t1, W_t2, b_t2);
    table4_k<<<4, 128>>>(emb, W_node, b_node);
    h_init_k<<<cdiv((long)BB * NN * HH, 256), 256>>>(types);
    init_x_k<<<cdiv((long)BB * NN * 3, 256), 256>>>(x);
    zero_i_k<<<cdiv(NN, 256), 256>>>(p_deg, NN);
    deg_count_k<<<cdiv(EE, 256), 256>>>(bonds);
    scan_k<<<1, 256>>>();
    fill_k<<<cdiv(EE, 256), 256>>>(bonds);

    const int gridE = BB * EE / 128;  // 2500
    const int gridN = BB * NN / 128;  // 1250

    for (int l = 0; l < LL; l++) {
        zero_f_k<<<cdiv((long)BB * NN * 3, 256), 256>>>(p_cupd, (long)BB * NN * 3);
        edge_geom_k<<<cdiv((long)BB * EE, 256), 256>>>(bonds);

        edge_fused_k<<<gridE, 256, EDGE_SMEM>>>(
            Wm1 + (long)l * 257 * 128, bm1 + l * 128,
            Wm1 + ((long)l * 257 + 256) * 128,
            Wm2 + (long)l * 16384, bm2 + l * 128,
            Wc1 + (long)l * 16384, bc1 + l * 128, Wc2 + l * 128, bonds);

        agg_gather_k<<<cdiv((long)BB * NN * 32, 256), 256>>>();

        node_fused_k<<<gridN, 256, NODE_SMEM>>>(
            Wn1 + (long)l * 256 * 128, bn1 + l * 128,
            Wn2 + (long)l * 16384, bn2 + l * 128);

        x_update_k<<<cdiv((long)BB * NN * 3, 256), 256>>>();
    }

    out_fused_k<<<gridN, 256, OUT_SMEM>>>(Wo1, bo1, Wo2, bo2, x, out);
}

// round 5
// speedup vs baseline: 1.3440x; 1.3440x over previous
#include <cuda_runtime.h>
#include <mma.h>
#include <math.h>
#include <stdint.h>

using namespace nvcuda;

#define BB 8
#define NN 20000
#define EE 40000
#define HH 128
#define TT 64
#define LL 4

__device__ __forceinline__ uint32_t f2tf(float f) {
    uint32_t u;
    asm("cvt.rna.tf32.f32 %0, %1;" : "=r"(u) : "f"(f));
    return u;
}
__device__ __forceinline__ float silu_f(float v) { return v / (1.f + __expf(-v)); }

// ---------------- scratch (static device globals) --------------------------
__device__ float g_temb[BB * HH];
__device__ float g_table4[4 * HH];
__device__ float g_h[BB * NN * HH];
__device__ float g_agg[BB * NN * HH];
__device__ float g_x[BB * NN * 3];
__device__ float g_cupd[BB * NN * 3];
__device__ float g_dist[BB * EE];
__device__ float g_cdn[BB * EE * 3];
__device__ float g_m[BB * EE * HH];
__device__ int   g_deg[NN];
__device__ int   g_off[NN + 1];
__device__ int   g_cur[NN];
__device__ int   g_csr[2 * EE];

// ---------------- shared wmma helpers --------------------------------------
#define LDT 136   // tile leading dim (floats)
#define LDA 36    // stage-1 A staging leading dim (aliases front of tile)

using FragC = wmma::fragment<wmma::accumulator, 16, 16, 8, float>;
using FragA = wmma::fragment<wmma::matrix_a, 16, 16, 8, wmma::precision::tf32, wmma::row_major>;
using FragB = wmma::fragment<wmma::matrix_b, 16, 16, 8, wmma::precision::tf32, wmma::row_major>;

// load 32 k-rows x 128 cols of W (K-major), tf32-round, into Bs[32][LDT]
__device__ __forceinline__ void stage_B(float* Bs, const float* __restrict__ W,
                                        int k0, int tid)
{
    const int bkrow = tid >> 3;
    const int bnc   = (tid & 7) * 16;
    const float* wbase = W + (long)(k0 + bkrow) * 128 + bnc;
#pragma unroll
    for (int q = 0; q < 4; q++) {
        float4 v = *(const float4*)(wbase + q * 4);
        uint4 bv;
        bv.x = f2tf(v.x); bv.y = f2tf(v.y); bv.z = f2tf(v.z); bv.w = f2tf(v.w);
        *(uint4*)(Bs + bkrow * LDT + bnc + q * 4) = bv;
    }
}

__device__ __forceinline__ void mma_chunk(FragC c[2][4], const float* Asrc, int lda,
                                          const float* Bs, int wm, int wn)
{
#pragma unroll
    for (int kk = 0; kk < 32; kk += 8) {
        FragA a[2];
        FragB b[4];
#pragma unroll
        for (int i = 0; i < 2; i++)
            wmma::load_matrix_sync(a[i], Asrc + (wm * 32 + i * 16) * lda + kk, lda);
#pragma unroll
        for (int j = 0; j < 4; j++)
            wmma::load_matrix_sync(b[j], Bs + kk * LDT + wn * 64 + j * 16, LDT);
#pragma unroll
        for (int i = 0; i < 2; i++)
#pragma unroll
            for (int j = 0; j < 4; j++)
                wmma::mma_sync(c[i][j], a[i], b[j], c[i][j]);
    }
}

__device__ __forceinline__ void zero_c(FragC c[2][4])
{
#pragma unroll
    for (int i = 0; i < 2; i++)
#pragma unroll
        for (int j = 0; j < 4; j++) wmma::fill_fragment(c[i][j], 0.f);
}

__device__ __forceinline__ void store_c(FragC c[2][4], float* T, int wm, int wn)
{
#pragma unroll
    for (int i = 0; i < 2; i++)
#pragma unroll
        for (int j = 0; j < 4; j++)
            wmma::store_matrix_sync(T + (wm * 32 + i * 16) * LDT + wn * 64 + j * 16,
                                    c[i][j], LDT, wmma::mem_row_major);
}

// single tile buffer + B buffer: 2 CTAs/SM
#define TILE_SMEM ((128 * LDT + 32 * LDT) * 4)   // 87040 B

// ---------------- fused edge kernel ----------------------------------------
// m1 = silu([h_src|h_dst]@Wm1 + dist*w256 + bm1)   (K=256, gathered A)
// m  = silu(m1@Wm2 + bm2)  -> g_m (global) and smem
// c1 = silu(m@Wc1 + bc1); cw = c1.Wc2 ; coord atomics
__global__ void __launch_bounds__(256, 2)
edge_fused_k(const float* __restrict__ Wm1, const float* __restrict__ bm1,
             const float* __restrict__ w256,
             const float* __restrict__ Wm2, const float* __restrict__ bm2,
             const float* __restrict__ Wc1, const float* __restrict__ bc1,
             const float* __restrict__ Wc2, const int* __restrict__ bonds)
{
    extern __shared__ float dyn[];
    float* T  = dyn;                 // [128][LDT]
    float* As = dyn;                 // aliases front of T (dead before store_c)
    float* Bs = dyn + 128 * LDT;     // [32][LDT]

    __shared__ float b1s[128], b2s[128], bc1s[128], wc2s[128], wds[128];
    __shared__ const float* pA0[128];
    __shared__ const float* pA1[128];

    const int tid = threadIdx.x;
    const int wid = tid >> 5;
    const int wm = wid & 3, wn = wid >> 2;
    const long row0 = (long)blockIdx.x * 128;

    if (tid < 128) {
        b1s[tid] = bm1[tid]; b2s[tid] = bm2[tid];
        bc1s[tid] = bc1[tid]; wc2s[tid] = Wc2[tid]; wds[tid] = w256[tid];
        long gr = row0 + tid;
        int b = (int)(gr / EE), e = (int)(gr - (long)b * EE);
        int s = bonds[2 * e], d = bonds[2 * e + 1];
        pA0[tid] = g_h + ((long)b * NN + s) * HH;
        pA1[tid] = g_h + ((long)b * NN + d) * HH;
    }
    __syncthreads();

    FragC c[2][4];
    zero_c(c);
    const int arow = tid >> 1;
    const int akb  = (tid & 1) * 16;

    // ---- stage 1: K=256 gather GEMM ----
    for (int k0 = 0; k0 < 256; k0 += 32) {
        const float* abase = ((k0 < 128) ? pA0[arow] : pA1[arow]) + (k0 & 127) + akb;
#pragma unroll
        for (int q = 0; q < 4; q++) {
            float4 v = *(const float4*)(abase + q * 4);
            uint4 av;
            av.x = f2tf(v.x); av.y = f2tf(v.y); av.z = f2tf(v.z); av.w = f2tf(v.w);
            *(uint4*)(As + arow * LDA + akb + q * 4) = av;
        }
        stage_B(Bs, Wm1, k0, tid);
        __syncthreads();
        mma_chunk(c, As, LDA, Bs, wm, wn);
        __syncthreads();
    }
    store_c(c, T, wm, wn);
    __syncthreads();
    {   // silu(+bias+dist term), tf32-round in place
        const int row = tid >> 1, cb = (tid & 1) * 64;
        const float dv = g_dist[row0 + row];
        float* p = T + row * LDT + cb;
#pragma unroll
        for (int j = 0; j < 64; j++) {
            float v = silu_f(p[j] + b1s[cb + j] + dv * wds[cb + j]);
            ((uint32_t*)p)[j] = f2tf(v);
        }
    }
    __syncthreads();

    // ---- stage 2: m = silu(m1@Wm2+b) ----
    zero_c(c);
    for (int k0 = 0; k0 < 128; k0 += 32) {
        stage_B(Bs, Wm2, k0, tid);
        __syncthreads();
        mma_chunk(c, T + k0, LDT, Bs, wm, wn);
        __syncthreads();
    }
    store_c(c, T, wm, wn);
    __syncthreads();
    {   // silu, write g_m (fp32), tf32 in smem
        const int row = tid >> 1, cb = (tid & 1) * 64;
        const long gr = row0 + row;
        float* p = T + row * LDT + cb;
        float* gm = g_m + gr * HH + cb;
#pragma unroll
        for (int j = 0; j < 64; j += 4) {
            float4 o;
            o.x = silu_f(p[j + 0] + b2s[cb + j + 0]);
            o.y = silu_f(p[j + 1] + b2s[cb + j + 1]);
            o.z = silu_f(p[j + 2] + b2s[cb + j + 2]);
            o.w = silu_f(p[j + 3] + b2s[cb + j + 3]);
            *(float4*)(gm + j) = o;
            ((uint32_t*)p)[j + 0] = f2tf(o.x);
            ((uint32_t*)p)[j + 1] = f2tf(o.y);
            ((uint32_t*)p)[j + 2] = f2tf(o.z);
            ((uint32_t*)p)[j + 3] = f2tf(o.w);
        }
    }
    __syncthreads();

    // ---- stage 3: c1 = silu(m@Wc1+b); cw = c1.Wc2; coord atomics ----
    zero_c(c);
    for (int k0 = 0; k0 < 128; k0 += 32) {
        stage_B(Bs, Wc1, k0, tid);
        __syncthreads();
        mma_chunk(c, T + k0, LDT, Bs, wm, wn);
        __syncthreads();
    }
    store_c(c, T, wm, wn);
    __syncthreads();
    if (tid < 128) {
        const float* crow = T + tid * LDT;
        float cw = 0.f;
#pragma unroll 16
        for (int col = 0; col < 128; col++)
            cw += silu_f(crow[col] + bc1s[col]) * wc2s[col];
        long gr = row0 + tid;
        int b = (int)(gr / EE), e = (int)(gr - (long)b * EE);
        int s = bonds[2 * e], d = bonds[2 * e + 1];
        const float* cd = g_cdn + gr * 3;
#pragma unroll
        for (int cc = 0; cc < 3; cc++) {
            float u = cd[cc] * cw;
            atomicAdd(&g_cupd[((long)b * NN + d) * 3 + cc], u);
            atomicAdd(&g_cupd[((long)b * NN + s) * 3 + cc], -u);
        }
    }
}

// ---------------- fused node kernel ----------------------------------------
// n1 = silu([h|agg]@Wn1 + bn1) (K=256); h = h + n1@Wn2 + bn2
__global__ void __launch_bounds__(256, 2)
node_fused_k(const float* __restrict__ Wn1, const float* __restrict__ bn1,
             const float* __restrict__ Wn2, const float* __restrict__ bn2)
{
    extern __shared__ float dyn[];
    float* T  = dyn;
    float* As = dyn;
    float* Bs = dyn + 128 * LDT;

    __shared__ float b1s[128], b2s[128];

    const int tid = threadIdx.x;
    const int wid = tid >> 5;
    const int wm = wid & 3, wn = wid >> 2;
    const long row0 = (long)blockIdx.x * 128;

    if (tid < 128) { b1s[tid] = bn1[tid]; b2s[tid] = bn2[tid]; }
    __syncthreads();

    FragC c[2][4];
    zero_c(c);
    const int arow = tid >> 1;
    const int akb  = (tid & 1) * 16;

    for (int k0 = 0; k0 < 256; k0 += 32) {
        const long gr = row0 + arow;
        const float* abase = ((k0 < 128) ? (g_h + gr * HH) : (g_agg + gr * HH)) + (k0 & 127) + akb;
#pragma unroll
        for (int q = 0; q < 4; q++) {
            float4 v = *(const float4*)(abase + q * 4);
            uint4 av;
            av.x = f2tf(v.x); av.y = f2tf(v.y); av.z = f2tf(v.z); av.w = f2tf(v.w);
            *(uint4*)(As + arow * LDA + akb + q * 4) = av;
        }
        stage_B(Bs, Wn1, k0, tid);
        __syncthreads();
        mma_chunk(c, As, LDA, Bs, wm, wn);
        __syncthreads();
    }
    store_c(c, T, wm, wn);
    __syncthreads();
    {
        const int row = tid >> 1, cb = (tid & 1) * 64;
        float* p = T + row * LDT + cb;
#pragma unroll
        for (int j = 0; j < 64; j++)
            ((uint32_t*)p)[j] = f2tf(silu_f(p[j] + b1s[cb + j]));
    }
    __syncthreads();

    zero_c(c);
    for (int k0 = 0; k0 < 128; k0 += 32) {
        stage_B(Bs, Wn2, k0, tid);
        __syncthreads();
        mma_chunk(c, T + k0, LDT, Bs, wm, wn);
        __syncthreads();
    }
    store_c(c, T, wm, wn);
    __syncthreads();
    {
        const int row = tid >> 1, cb = (tid & 1) * 64;
        const long gr = row0 + row;
        const float* p = T + row * LDT + cb;
        float* hp = g_h + gr * HH + cb;
#pragma unroll
        for (int j = 0; j < 64; j += 4) {
            float4 hv = *(const float4*)(hp + j);
            float4 o;
            o.x = hv.x + p[j + 0] + b2s[cb + j + 0];
            o.y = hv.y + p[j + 1] + b2s[cb + j + 1];
            o.z = hv.z + p[j + 2] + b2s[cb + j + 2];
            o.w = hv.w + p[j + 3] + b2s[cb + j + 3];
            *(float4*)(hp + j) = o;
        }
    }
}

// ---------------- fused output kernel --------------------------------------
// o1 = silu(h@Wo1 + bo1); out = o1@Wo2 + bo2 + (x_final - x_in)
__global__ void __launch_bounds__(256, 2)
out_fused_k(const float* __restrict__ Wo1, const float* __restrict__ bo1,
            const float* __restrict__ Wo2, const float* __restrict__ bo2,
            const float* __restrict__ x_in, float* __restrict__ out)
{
    extern __shared__ float dyn[];
    float* T  = dyn;
    float* As = dyn;
    float* Bs = dyn + 128 * LDT;

    __shared__ float b1s[128];
    __shared__ float wo2s[128 * 3];

    const int tid = threadIdx.x;
    const int wid = tid >> 5;
    const int wm = wid & 3, wn = wid >> 2;
    const long row0 = (long)blockIdx.x * 128;

    if (tid < 128) b1s[tid] = bo1[tid];
    for (int i = tid; i < 384; i += 256) wo2s[i] = Wo2[i];
    __syncthreads();

    FragC c[2][4];
    zero_c(c);
    const int arow = tid >> 1;
    const int akb  = (tid & 1) * 16;

    for (int k0 = 0; k0 < 128; k0 += 32) {
        const float* abase = g_h + (row0 + arow) * (long)HH + k0 + akb;
#pragma unroll
        for (int q = 0; q < 4; q++) {
            float4 v = *(const float4*)(abase + q * 4);
            uint4 av;
            av.x = f2tf(v.x); av.y = f2tf(v.y); av.z = f2tf(v.z); av.w = f2tf(v.w);
            *(uint4*)(As + arow * LDA + akb + q * 4) = av;
        }
        stage_B(Bs, Wo1, k0, tid);
        __syncthreads();
        mma_chunk(c, As, LDA, Bs, wm, wn);
        __syncthreads();
    }
    store_c(c, T, wm, wn);
    __syncthreads();
    if (tid < 128) {
        const float* crow = T + tid * LDT;
        float a0 = 0.f, a1 = 0.f, a2 = 0.f;
#pragma unroll 16
        for (int col = 0; col < 128; col++) {
            float v = silu_f(crow[col] + b1s[col]);
            a0 += v * wo2s[col * 3 + 0];
            a1 += v * wo2s[col * 3 + 1];
            a2 += v * wo2s[col * 3 + 2];
        }
        long gr = row0 + tid;
        long base = gr * 3;
        out[base + 0] = a0 + bo2[0] + g_x[base + 0] - x_in[base + 0];
        out[base + 1] = a1 + bo2[1] + g_x[base + 1] - x_in[base + 1];
        out[base + 2] = a2 + bo2[2] + g_x[base + 2] - x_in[base + 2];
    }
}

// ---------------- small kernels -------------------------------------------
__global__ void time_embed_k(const float* __restrict__ t,
                             const float* __restrict__ W1, const float* __restrict__ b1,
                             const float* __restrict__ W2, const float* __restrict__ b2)
{
    __shared__ float te[BB][TT];
    __shared__ float s1[BB][HH];
    int tid = threadIdx.x;
    const int half = TT / 2;
    for (int idx = tid; idx < BB * TT; idx += 128) {
        int b = idx / TT, k = idx % TT;
        int kk = (k < half) ? k : (k - half);
        float f = __expf((float)kk * (-logf(10000.f) / (float)(half - 1)));
        float a = t[b] * f;
        te[b][k] = (k < half) ? sinf(a) : cosf(a);
    }
    __syncthreads();
    for (int b = 0; b < BB; b++) {
        float acc = b1[tid];
        for (int k = 0; k < TT; k++) acc += te[b][k] * W1[k * HH + tid];
        s1[b][tid] = silu_f(acc);
    }
    __syncthreads();
    for (int b = 0; b < BB; b++) {
        float acc = b2[tid];
        for (int k = 0; k < HH; k++) acc += s1[b][k] * W2[k * HH + tid];
        g_temb[b * HH + tid] = acc;
    }
}

__global__ void table4_k(const float* __restrict__ emb,
                         const float* __restrict__ Wn, const float* __restrict__ bn)
{
    int a = blockIdx.x, j = threadIdx.x;
    float acc = bn[j];
    for (int k = 0; k < HH; k++) acc += emb[a * HH + k] * Wn[k * HH + j];
    g_table4[a * HH + j] = acc;
}

__global__ void h_init_k(const int* __restrict__ types)
{
    long idx = (long)blockIdx.x * 256 + threadIdx.x;
    if (idx >= (long)BB * NN * HH) return;
    int j = (int)(idx & 127);
    long bn = idx >> 7;
    int n = (int)(bn % NN), b = (int)(bn / NN);
    g_h[idx] = g_table4[types[n] * HH + j] + g_temb[b * HH + j];
}

__global__ void init_x_k(const float* __restrict__ x)
{
    int idx = blockIdx.x * 256 + threadIdx.x;
    if (idx < BB * NN * 3) g_x[idx] = x[idx];
}

__global__ void zero_f_k(float* __restrict__ p, long n)
{
    long idx = (long)blockIdx.x * 256 + threadIdx.x;
    if (idx < n) p[idx] = 0.f;
}
__global__ void zero_i_k(int* __restrict__ p, int n)
{
    int idx = blockIdx.x * 256 + threadIdx.x;
    if (idx < n) p[idx] = 0;
}

__global__ void deg_count_k(const int* __restrict__ bonds)
{
    int e = blockIdx.x * 256 + threadIdx.x;
    if (e >= EE) return;
    atomicAdd(&g_deg[bonds[2 * e]], 1);
    atomicAdd(&g_deg[bonds[2 * e + 1]], 1);
}

__global__ void scan_k()
{
    __shared__ int sh[256];
    __shared__ int base;
    int tid = threadIdx.x;
    if (tid == 0) base = 0;
    __syncthreads();
    for (int i0 = 0; i0 < NN; i0 += 256) {
        int i = i0 + tid;
        int v = (i < NN) ? g_deg[i] : 0;
        sh[tid] = v;
        __syncthreads();
        for (int o = 1; o < 256; o <<= 1) {
            int t = (tid >= o) ? sh[tid - o] : 0;
            __syncthreads();
            sh[tid] += t;
            __syncthreads();
        }
        int excl = base + sh[tid] - v;
        if (i < NN) { g_off[i] = excl; g_cur[i] = excl; }
        __syncthreads();
        if (tid == 255) base += sh[255];
        __syncthreads();
    }
    if (tid == 0) g_off[NN] = base;
}

__global__ void fill_k(const int* __restrict__ bonds)
{
    int e = blockIdx.x * 256 + threadIdx.x;
    if (e >= EE) return;
    int s = bonds[2 * e], d = bonds[2 * e + 1];
    int p = atomicAdd(&g_cur[s], 1); g_csr[p] = e;
    int q = atomicAdd(&g_cur[d], 1); g_csr[q] = e;
}

__global__ void edge_geom_k(const int* __restrict__ bonds)
{
    int idx = blockIdx.x * 256 + threadIdx.x;
    if (idx >= BB * EE) return;
    int b = idx / EE, e = idx - b * EE;
    int s = bonds[2 * e], d = bonds[2 * e + 1];
    const float* xs = g_x + ((long)b * NN + s) * 3;
    const float* xd = g_x + ((long)b * NN + d) * 3;
    float dx = xd[0] - xs[0], dy = xd[1] - xs[1], dz = xd[2] - xs[2];
    float dist = sqrtf(dx * dx + dy * dy + dz * dz);
    g_dist[idx] = dist;
    float inv = 1.f / (dist + 1e-8f);
    g_cdn[idx * 3 + 0] = dx * inv;
    g_cdn[idx * 3 + 1] = dy * inv;
    g_cdn[idx * 3 + 2] = dz * inv;
}

// agg[b,n,:] = sum over incident edges of m[b,e,:] (CSR gather, no atomics)
__global__ void agg_gather_k()
{
    int warp = (blockIdx.x * 256 + threadIdx.x) >> 5;
    int lane = threadIdx.x & 31;
    if (warp >= BB * NN) return;
    int b = warp / NN, n = warp - b * NN;
    int o0 = g_off[n], o1 = g_off[n + 1];
    float4 acc = make_float4(0.f, 0.f, 0.f, 0.f);
    for (int j = o0; j < o1; j++) {
        int e = g_csr[j];
        float4 v = ((const float4*)(g_m + ((long)b * EE + e) * HH))[lane];
        acc.x += v.x; acc.y += v.y; acc.z += v.z; acc.w += v.w;
    }
    ((float4*)(g_agg + (long)warp * HH))[lane] = acc;
}

__global__ void x_update_k()
{
    int idx = blockIdx.x * 256 + threadIdx.x;
    if (idx >= BB * NN * 3) return;
    int n = (idx / 3) % NN;
    g_x[idx] += g_cupd[idx] / fmaxf((float)g_deg[n], 1.f);
}

// ---------------- launch ---------------------------------------------------
static inline int cdiv(long n, int b) { return (int)((n + b - 1) / b); }

extern "C" void kernel_launch(void* const* d_in, const int* in_sizes, int n_in,
                              void* d_out, int out_size)
{
    const float* x      = (const float*)d_in[0];
    const float* t      = (const float*)d_in[1];
    const int*   types  = (const int*)d_in[2];
    const int*   bonds  = (const int*)d_in[3];
    const float* emb    = (const float*)d_in[4];
    const float* W_t1   = (const float*)d_in[5];
    const float* b_t1   = (const float*)d_in[6];
    const float* W_t2   = (const float*)d_in[7];
    const float* b_t2   = (const float*)d_in[8];
    const float* W_node = (const float*)d_in[9];
    const float* b_node = (const float*)d_in[10];
    const float* Wm1    = (const float*)d_in[11];
    const float* bm1    = (const float*)d_in[12];
    const float* Wm2    = (const float*)d_in[13];
    const float* bm2    = (const float*)d_in[14];
    const float* Wn1    = (const float*)d_in[15];
    const float* bn1    = (const float*)d_in[16];
    const float* Wn2    = (const float*)d_in[17];
    const float* bn2    = (const float*)d_in[18];
    const float* Wc1    = (const float*)d_in[19];
    const float* bc1    = (const float*)d_in[20];
    const float* Wc2    = (const float*)d_in[21];
    const float* Wo1    = (const float*)d_in[22];
    const float* bo1    = (const float*)d_in[23];
    const float* Wo2    = (const float*)d_in[24];
    const float* bo2    = (const float*)d_in[25];
    float* out = (float*)d_out;

    float *p_cupd;
    int *p_deg;
    cudaGetSymbolAddress((void**)&p_cupd, g_cupd);
    cudaGetSymbolAddress((void**)&p_deg, g_deg);

    cudaFuncSetAttribute(edge_fused_k, cudaFuncAttributeMaxDynamicSharedMemorySize, TILE_SMEM);
    cudaFuncSetAttribute(node_fused_k, cudaFuncAttributeMaxDynamicSharedMemorySize, TILE_SMEM);
    cudaFuncSetAttribute(out_fused_k, cudaFuncAttributeMaxDynamicSharedMemorySize, TILE_SMEM);

    // embeddings, init, CSR
    time_embed_k<<<1, 128>>>(t, W_t1, b_t1, W_t2, b_t2);
    table4_k<<<4, 128>>>(emb, W_node, b_node);
    h_init_k<<<cdiv((long)BB * NN * HH, 256), 256>>>(types);
    init_x_k<<<cdiv((long)BB * NN * 3, 256), 256>>>(x);
    zero_i_k<<<cdiv(NN, 256), 256>>>(p_deg, NN);
    deg_count_k<<<cdiv(EE, 256), 256>>>(bonds);
    scan_k<<<1, 256>>>();
    fill_k<<<cdiv(EE, 256), 256>>>(bonds);

    const int gridE = BB * EE / 128;  // 2500
    const int gridN = BB * NN / 128;  // 1250

    for (int l = 0; l < LL; l++) {
        zero_f_k<<<cdiv((long)BB * NN * 3, 256), 256>>>(p_cupd, (long)BB * NN * 3);
        edge_geom_k<<<cdiv((long)BB * EE, 256), 256>>>(bonds);

        edge_fused_k<<<gridE, 256, TILE_SMEM>>>(
            Wm1 + (long)l * 257 * 128, bm1 + l * 128,
            Wm1 + ((long)l * 257 + 256) * 128,
            Wm2 + (long)l * 16384, bm2 + l * 128,
            Wc1 + (long)l * 16384, bc1 + l * 128, Wc2 + l * 128, bonds);

        agg_gather_k<<<cdiv((long)BB * NN * 32, 256), 256>>>();

        node_fused_k<<<gridN, 256, TILE_SMEM>>>(
            Wn1 + (long)l * 256 * 128, bn1 + l * 128,
            Wn2 + (long)l * 16384, bn2 + l * 128);

        x_update_k<<<cdiv((long)BB * NN * 3, 256), 256>>>();
    }

    out_fused_k<<<gridN, 256, TILE_SMEM>>>(Wo1, bo1, Wo2, bo2, x, out);
}

// round 6
// speedup vs baseline: 1.3834x; 1.0293x over previous
#include <cuda_runtime.h>
#include <mma.h>
#include <math.h>
#include <stdint.h>

using namespace nvcuda;

#define BB 8
#define NN 20000
#define EE 40000
#define HH 128
#define TT 64
#define LL 4

__device__ __forceinline__ uint32_t f2tf(float f) {
    uint32_t u;
    asm("cvt.rna.tf32.f32 %0, %1;" : "=r"(u) : "f"(f));
    return u;
}
__device__ __forceinline__ float silu_f(float v) { return v / (1.f + __expf(-v)); }
__device__ __forceinline__ uint32_t s2u(const void* p) {
    uint32_t a;
    asm("{ .reg .u64 t; cvta.to.shared.u64 t, %1; cvt.u32.u64 %0, t; }" : "=r"(a) : "l"(p));
    return a;
}
__device__ __forceinline__ void cp16(uint32_t dst, const void* src) {
    asm volatile("cp.async.cg.shared.global [%0], [%1], 16;\n" :: "r"(dst), "l"(src));
}
#define CP_COMMIT() asm volatile("cp.async.commit_group;\n" ::: "memory")
template <int N> __device__ __forceinline__ void cp_wait() {
    asm volatile("cp.async.wait_group %0;\n" :: "n"(N) : "memory");
}

// ---------------- scratch (static device globals) --------------------------
__device__ float g_temb[BB * HH];
__device__ float g_table4[4 * HH];
__device__ float g_h[BB * NN * HH];
__device__ float g_htf[BB * NN * HH];    // tf32-rounded shadow of h
__device__ float g_agg[BB * NN * HH];    // tf32-rounded at store
__device__ float g_x[BB * NN * 3];
__device__ float g_cupd[BB * NN * 3];
__device__ float g_dist[BB * EE];
__device__ float g_cdn[BB * EE * 3];
__device__ float g_m[BB * EE * HH];      // fp32 (agg sums in fp32)
__device__ int   g_deg[NN];
__device__ int   g_off[NN + 1];
__device__ int   g_cur[NN];
__device__ int   g_csr[2 * EE];
// tf32-rounded weights
__device__ float g_wm1[4 * 257 * 128];
__device__ float g_wm2[4 * 128 * 128];
__device__ float g_wc1[4 * 128 * 128];
__device__ float g_wn1[4 * 256 * 128];
__device__ float g_wn2[4 * 128 * 128];
__device__ float g_wo1[128 * 128];

// ---------------- wmma helpers ---------------------------------------------
#define LDT 136
#define LDAs 36

using FragC = wmma::fragment<wmma::accumulator, 16, 16, 8, float>;
using FragA = wmma::fragment<wmma::matrix_a, 16, 16, 8, wmma::precision::tf32, wmma::row_major>;
using FragB = wmma::fragment<wmma::matrix_b, 16, 16, 8, wmma::precision::tf32, wmma::row_major>;

__device__ __forceinline__ void mma_chunk(FragC c[2][4], const float* Asrc, int lda,
                                          const float* Bs, int wm, int wn)
{
#pragma unroll
    for (int kk = 0; kk < 32; kk += 8) {
        FragA a[2];
        FragB b[4];
#pragma unroll
        for (int i = 0; i < 2; i++)
            wmma::load_matrix_sync(a[i], Asrc + (wm * 32 + i * 16) * lda + kk, lda);
#pragma unroll
        for (int j = 0; j < 4; j++)
            wmma::load_matrix_sync(b[j], Bs + kk * LDT + wn * 64 + j * 16, LDT);
#pragma unroll
        for (int i = 0; i < 2; i++)
#pragma unroll
            for (int j = 0; j < 4; j++)
                wmma::mma_sync(c[i][j], a[i], b[j], c[i][j]);
    }
}
__device__ __forceinline__ void zero_c(FragC c[2][4])
{
#pragma unroll
    for (int i = 0; i < 2; i++)
#pragma unroll
        for (int j = 0; j < 4; j++) wmma::fill_fragment(c[i][j], 0.f);
}
__device__ __forceinline__ void store_c(FragC c[2][4], float* T, int wm, int wn)
{
#pragma unroll
    for (int i = 0; i < 2; i++)
#pragma unroll
        for (int j = 0; j < 4; j++)
            wmma::store_matrix_sync(T + (wm * 32 + i * 16) * LDT + wn * 64 + j * 16,
                                    c[i][j], LDT, wmma::mem_row_major);
}

// issue one 32-row B chunk via cp.async (pre-rounded weights)
__device__ __forceinline__ void issue_B(const float* __restrict__ W, int k0,
                                        float* Bsb, int tid)
{
    const int bkrow = tid >> 3;
    const int bnc   = (tid & 7) * 16;
    const float* src = W + (long)(k0 + bkrow) * 128 + bnc;
    uint32_t dst = s2u(Bsb + bkrow * LDT + bnc);
#pragma unroll
    for (int q = 0; q < 4; q++) cp16(dst + q * 16, src + q * 4);
}

// dyn smem: T[128*LDT] + Bs0[32*LDT] + Bs1[32*LDT]; As ping-pong aliases T
#define FUSE_SMEM ((128 * LDT + 64 * LDT) * 4)   // 104448 B

// ---------------- fused edge kernel ----------------------------------------
__global__ void __launch_bounds__(256, 2)
edge_fused_k(const float* __restrict__ Wm1tf, const float* __restrict__ bm1,
             const float* __restrict__ w256,
             const float* __restrict__ Wm2tf, const float* __restrict__ bm2,
             const float* __restrict__ Wc1tf, const float* __restrict__ bc1,
             const float* __restrict__ Wc2, const int* __restrict__ bonds)
{
    extern __shared__ float dyn[];
    float* T   = dyn;
    float* Bs0 = dyn + 128 * LDT;
    float* Bs1 = Bs0 + 32 * LDT;
    float* As0 = T;
    float* As1 = T + 128 * LDAs;

    __shared__ float b1s[128], b2s[128], bc1s[128], wc2s[128], wds[128];
    __shared__ const float* pA0[128];
    __shared__ const float* pA1[128];

    const int tid = threadIdx.x;
    const int wid = tid >> 5;
    const int wm = wid & 3, wn = wid >> 2;
    const long row0 = (long)blockIdx.x * 128;

    if (tid < 128) {
        b1s[tid] = bm1[tid]; b2s[tid] = bm2[tid];
        bc1s[tid] = bc1[tid]; wc2s[tid] = Wc2[tid]; wds[tid] = w256[tid];
        long gr = row0 + tid;
        int b = (int)(gr / EE), e = (int)(gr - (long)b * EE);
        int s = bonds[2 * e], d = bonds[2 * e + 1];
        pA0[tid] = g_htf + ((long)b * NN + s) * HH;
        pA1[tid] = g_htf + ((long)b * NN + d) * HH;
    }
    __syncthreads();

    const int arow = tid >> 1;
    const int akb  = (tid & 1) * 16;

    auto issue_A = [&](int ch, float* Asb) {
        int k0 = ch << 5;
        const float* src = ((k0 < 128) ? pA0[arow] : pA1[arow]) + (k0 & 127) + akb;
        uint32_t dst = s2u(Asb + arow * LDAs + akb);
#pragma unroll
        for (int q = 0; q < 4; q++) cp16(dst + q * 16, src + q * 4);
    };

    FragC c[2][4];

    // ---- stage 1: m1 = silu(gather @ Wm1 + dist*w256 + b), K=256 ----
    zero_c(c);
    issue_A(0, As0); issue_B(Wm1tf, 0, Bs0, tid); CP_COMMIT();
    issue_A(1, As1); issue_B(Wm1tf, 32, Bs1, tid); CP_COMMIT();
    for (int ch = 0; ch < 8; ch++) {
        if (ch == 7) cp_wait<0>(); else cp_wait<1>();
        __syncthreads();
        mma_chunk(c, (ch & 1) ? As1 : As0, LDAs, (ch & 1) ? Bs1 : Bs0, wm, wn);
        __syncthreads();
        if (ch + 2 < 8) {
            issue_A(ch + 2, (ch & 1) ? As1 : As0);
            issue_B(Wm1tf, (ch + 2) * 32, (ch & 1) ? Bs1 : Bs0, tid);
            CP_COMMIT();
        }
    }
    store_c(c, T, wm, wn);
    __syncthreads();
    {
        const int row = tid >> 1, cb = (tid & 1) * 64;
        const float dv = g_dist[row0 + row];
        float* p = T + row * LDT + cb;
#pragma unroll
        for (int j = 0; j < 64; j++) {
            float v = silu_f(p[j] + b1s[cb + j] + dv * wds[cb + j]);
            ((uint32_t*)p)[j] = f2tf(v);
        }
    }
    __syncthreads();

    // ---- stage 2: m = silu(m1 @ Wm2 + b) ----
    zero_c(c);
    issue_B(Wm2tf, 0, Bs0, tid); CP_COMMIT();
    issue_B(Wm2tf, 32, Bs1, tid); CP_COMMIT();
    for (int ch = 0; ch < 4; ch++) {
        if (ch == 3) cp_wait<0>(); else cp_wait<1>();
        __syncthreads();
        mma_chunk(c, T + ch * 32, LDT, (ch & 1) ? Bs1 : Bs0, wm, wn);
        __syncthreads();
        if (ch + 2 < 4) { issue_B(Wm2tf, (ch + 2) * 32, (ch & 1) ? Bs1 : Bs0, tid); CP_COMMIT(); }
    }
    store_c(c, T, wm, wn);
    __syncthreads();
    {
        const int row = tid >> 1, cb = (tid & 1) * 64;
        const long gr = row0 + row;
        float* p = T + row * LDT + cb;
        float* gm = g_m + gr * HH + cb;
#pragma unroll
        for (int j = 0; j < 64; j += 4) {
            float4 o;
            o.x = silu_f(p[j + 0] + b2s[cb + j + 0]);
            o.y = silu_f(p[j + 1] + b2s[cb + j + 1]);
            o.z = silu_f(p[j + 2] + b2s[cb + j + 2]);
            o.w = silu_f(p[j + 3] + b2s[cb + j + 3]);
            *(float4*)(gm + j) = o;
            ((uint32_t*)p)[j + 0] = f2tf(o.x);
            ((uint32_t*)p)[j + 1] = f2tf(o.y);
            ((uint32_t*)p)[j + 2] = f2tf(o.z);
            ((uint32_t*)p)[j + 3] = f2tf(o.w);
        }
    }
    __syncthreads();

    // ---- stage 3: cw = silu(m @ Wc1 + b) . Wc2; coord atomics ----
    zero_c(c);
    issue_B(Wc1tf, 0, Bs0, tid); CP_COMMIT();
    issue_B(Wc1tf, 32, Bs1, tid); CP_COMMIT();
    for (int ch = 0; ch < 4; ch++) {
        if (ch == 3) cp_wait<0>(); else cp_wait<1>();
        __syncthreads();
        mma_chunk(c, T + ch * 32, LDT, (ch & 1) ? Bs1 : Bs0, wm, wn);
        __syncthreads();
        if (ch + 2 < 4) { issue_B(Wc1tf, (ch + 2) * 32, (ch & 1) ? Bs1 : Bs0, tid); CP_COMMIT(); }
    }
    store_c(c, T, wm, wn);
    __syncthreads();
    if (tid < 128) {
        const float* crow = T + tid * LDT;
        float cw = 0.f;
#pragma unroll 16
        for (int col = 0; col < 128; col++)
            cw += silu_f(crow[col] + bc1s[col]) * wc2s[col];
        long gr = row0 + tid;
        int b = (int)(gr / EE), e = (int)(gr - (long)b * EE);
        int s = bonds[2 * e], d = bonds[2 * e + 1];
        const float* cd = g_cdn + gr * 3;
#pragma unroll
        for (int cc = 0; cc < 3; cc++) {
            float u = cd[cc] * cw;
            atomicAdd(&g_cupd[((long)b * NN + d) * 3 + cc], u);
            atomicAdd(&g_cupd[((long)b * NN + s) * 3 + cc], -u);
        }
    }
}

// ---------------- fused node kernel ----------------------------------------
__global__ void __launch_bounds__(256, 2)
node_fused_k(const float* __restrict__ Wn1tf, const float* __restrict__ bn1,
             const float* __restrict__ Wn2tf, const float* __restrict__ bn2)
{
    extern __shared__ float dyn[];
    float* T   = dyn;
    float* Bs0 = dyn + 128 * LDT;
    float* Bs1 = Bs0 + 32 * LDT;
    float* As0 = T;
    float* As1 = T + 128 * LDAs;

    __shared__ float b1s[128], b2s[128];

    const int tid = threadIdx.x;
    const int wid = tid >> 5;
    const int wm = wid & 3, wn = wid >> 2;
    const long row0 = (long)blockIdx.x * 128;

    if (tid < 128) { b1s[tid] = bn1[tid]; b2s[tid] = bn2[tid]; }
    __syncthreads();

    const int arow = tid >> 1;
    const int akb  = (tid & 1) * 16;
    const long gra = row0 + arow;

    auto issue_A = [&](int ch, float* Asb) {
        int k0 = ch << 5;
        const float* src = ((k0 < 128) ? (g_htf + gra * HH) : (g_agg + gra * HH))
                           + (k0 & 127) + akb;
        uint32_t dst = s2u(Asb + arow * LDAs + akb);
#pragma unroll
        for (int q = 0; q < 4; q++) cp16(dst + q * 16, src + q * 4);
    };

    FragC c[2][4];

    // ---- stage 1: n1 = silu([h|agg] @ Wn1 + b), K=256 ----
    zero_c(c);
    issue_A(0, As0); issue_B(Wn1tf, 0, Bs0, tid); CP_COMMIT();
    issue_A(1, As1); issue_B(Wn1tf, 32, Bs1, tid); CP_COMMIT();
    for (int ch = 0; ch < 8; ch++) {
        if (ch == 7) cp_wait<0>(); else cp_wait<1>();
        __syncthreads();
        mma_chunk(c, (ch & 1) ? As1 : As0, LDAs, (ch & 1) ? Bs1 : Bs0, wm, wn);
        __syncthreads();
        if (ch + 2 < 8) {
            issue_A(ch + 2, (ch & 1) ? As1 : As0);
            issue_B(Wn1tf, (ch + 2) * 32, (ch & 1) ? Bs1 : Bs0, tid);
            CP_COMMIT();
        }
    }
    store_c(c, T, wm, wn);
    __syncthreads();
    {
        const int row = tid >> 1, cb = (tid & 1) * 64;
        float* p = T + row * LDT + cb;
#pragma unroll
        for (int j = 0; j < 64; j++)
            ((uint32_t*)p)[j] = f2tf(silu_f(p[j] + b1s[cb + j]));
    }
    __syncthreads();

    // ---- stage 2: h += n1 @ Wn2 + b (also refresh g_htf) ----
    zero_c(c);
    issue_B(Wn2tf, 0, Bs0, tid); CP_COMMIT();
    issue_B(Wn2tf, 32, Bs1, tid); CP_COMMIT();
    for (int ch = 0; ch < 4; ch++) {
        if (ch == 3) cp_wait<0>(); else cp_wait<1>();
        __syncthreads();
        mma_chunk(c, T + ch * 32, LDT, (ch & 1) ? Bs1 : Bs0, wm, wn);
        __syncthreads();
        if (ch + 2 < 4) { issue_B(Wn2tf, (ch + 2) * 32, (ch & 1) ? Bs1 : Bs0, tid); CP_COMMIT(); }
    }
    store_c(c, T, wm, wn);
    __syncthreads();
    {
        const int row = tid >> 1, cb = (tid & 1) * 64;
        const long gr = row0 + row;
        const float* p = T + row * LDT + cb;
        float* hp = g_h + gr * HH + cb;
        float* htf = g_htf + gr * HH + cb;
#pragma unroll
        for (int j = 0; j < 64; j += 4) {
            float4 hv = *(const float4*)(hp + j);
            float4 o;
            o.x = hv.x + p[j + 0] + b2s[cb + j + 0];
            o.y = hv.y + p[j + 1] + b2s[cb + j + 1];
            o.z = hv.z + p[j + 2] + b2s[cb + j + 2];
            o.w = hv.w + p[j + 3] + b2s[cb + j + 3];
            *(float4*)(hp + j) = o;
            uint4 tf;
            tf.x = f2tf(o.x); tf.y = f2tf(o.y); tf.z = f2tf(o.z); tf.w = f2tf(o.w);
            *(uint4*)(htf + j) = tf;
        }
    }
}

// ---------------- fused output kernel --------------------------------------
__global__ void __launch_bounds__(256, 2)
out_fused_k(const float* __restrict__ Wo1tf, const float* __restrict__ bo1,
            const float* __restrict__ Wo2, const float* __restrict__ bo2,
            const float* __restrict__ x_in, float* __restrict__ out)
{
    extern __shared__ float dyn[];
    float* T   = dyn;
    float* Bs0 = dyn + 128 * LDT;
    float* Bs1 = Bs0 + 32 * LDT;
    float* As0 = T;
    float* As1 = T + 128 * LDAs;

    __shared__ float b1s[128];
    __shared__ float wo2s[128 * 3];

    const int tid = threadIdx.x;
    const int wid = tid >> 5;
    const int wm = wid & 3, wn = wid >> 2;
    const long row0 = (long)blockIdx.x * 128;

    if (tid < 128) b1s[tid] = bo1[tid];
    for (int i = tid; i < 384; i += 256) wo2s[i] = Wo2[i];
    __syncthreads();

    const int arow = tid >> 1;
    const int akb  = (tid & 1) * 16;
    const long gra = row0 + arow;

    auto issue_A = [&](int ch, float* Asb) {
        const float* src = g_htf + gra * HH + (ch << 5) + akb;
        uint32_t dst = s2u(Asb + arow * LDAs + akb);
#pragma unroll
        for (int q = 0; q < 4; q++) cp16(dst + q * 16, src + q * 4);
    };

    FragC c[2][4];
    zero_c(c);
    issue_A(0, As0); issue_B(Wo1tf, 0, Bs0, tid); CP_COMMIT();
    issue_A(1, As1); issue_B(Wo1tf, 32, Bs1, tid); CP_COMMIT();
    for (int ch = 0; ch < 4; ch++) {
        if (ch == 3) cp_wait<0>(); else cp_wait<1>();
        __syncthreads();
        mma_chunk(c, (ch & 1) ? As1 : As0, LDAs, (ch & 1) ? Bs1 : Bs0, wm, wn);
        __syncthreads();
        if (ch + 2 < 4) {
            issue_A(ch + 2, (ch & 1) ? As1 : As0);
            issue_B(Wo1tf, (ch + 2) * 32, (ch & 1) ? Bs1 : Bs0, tid);
            CP_COMMIT();
        }
    }
    store_c(c, T, wm, wn);
    __syncthreads();
    if (tid < 128) {
        const float* crow = T + tid * LDT;
        float a0 = 0.f, a1 = 0.f, a2 = 0.f;
#pragma unroll 16
        for (int col = 0; col < 128; col++) {
            float v = silu_f(crow[col] + b1s[col]);
            a0 += v * wo2s[col * 3 + 0];
            a1 += v * wo2s[col * 3 + 1];
            a2 += v * wo2s[col * 3 + 2];
        }
        long base = (row0 + tid) * 3;
        out[base + 0] = a0 + bo2[0] + g_x[base + 0] - x_in[base + 0];
        out[base + 1] = a1 + bo2[1] + g_x[base + 1] - x_in[base + 1];
        out[base + 2] = a2 + bo2[2] + g_x[base + 2] - x_in[base + 2];
    }
}

// ---------------- setup kernels --------------------------------------------
// block 0: time embedding; block 1: node table; blocks >=2: weight tf32 round
__global__ void setupA_k(const float* __restrict__ t,
                         const float* __restrict__ W1, const float* __restrict__ b1,
                         const float* __restrict__ W2, const float* __restrict__ b2,
                         const float* __restrict__ emb,
                         const float* __restrict__ Wn, const float* __restrict__ bn,
                         const float* __restrict__ Wm1, const float* __restrict__ Wm2,
                         const float* __restrict__ Wc1, const float* __restrict__ Wn1,
                         const float* __restrict__ Wn2, const float* __restrict__ Wo1)
{
    const int tid = threadIdx.x;
    if (blockIdx.x == 0) {
        __shared__ float te[BB][TT];
        __shared__ float s1[BB][HH];
        const int half = TT / 2;
        for (int idx = tid; idx < BB * TT; idx += 256) {
            int b = idx / TT, k = idx % TT;
            int kk = (k < half) ? k : (k - half);
            float f = __expf((float)kk * (-logf(10000.f) / (float)(half - 1)));
            float a = t[b] * f;
            te[b][k] = (k < half) ? sinf(a) : cosf(a);
        }
        __syncthreads();
        if (tid < 128) {
            for (int b = 0; b < BB; b++) {
                float acc = b1[tid];
                for (int k = 0; k < TT; k++) acc += te[b][k] * W1[k * HH + tid];
                s1[b][tid] = silu_f(acc);
            }
        }
        __syncthreads();
        if (tid < 128) {
            for (int b = 0; b < BB; b++) {
                float acc = b2[tid];
                for (int k = 0; k < HH; k++) acc += s1[b][k] * W2[k * HH + tid];
                g_temb[b * HH + tid] = acc;
            }
        }
    } else if (blockIdx.x == 1) {
        for (int idx = tid; idx < 4 * HH; idx += 256) {
            int a = idx >> 7, j = idx & 127;
            float acc = bn[j];
            for (int k = 0; k < HH; k++) acc += emb[a * HH + k] * Wn[k * HH + j];
            g_table4[idx] = acc;
        }
    } else {
        long rid = (long)(blockIdx.x - 2) * 256 + tid;
        long rstride = (long)(gridDim.x - 2) * 256;
        for (long i = rid; i < 4L * 257 * 128; i += rstride) ((uint32_t*)g_wm1)[i] = f2tf(Wm1[i]);
        for (long i = rid; i < 4L * 128 * 128; i += rstride) ((uint32_t*)g_wm2)[i] = f2tf(Wm2[i]);
        for (long i = rid; i < 4L * 128 * 128; i += rstride) ((uint32_t*)g_wc1)[i] = f2tf(Wc1[i]);
        for (long i = rid; i < 4L * 256 * 128; i += rstride) ((uint32_t*)g_wn1)[i] = f2tf(Wn1[i]);
        for (long i = rid; i < 4L * 128 * 128; i += rstride) ((uint32_t*)g_wn2)[i] = f2tf(Wn2[i]);
        for (long i = rid; i < 128L * 128; i += rstride) ((uint32_t*)g_wo1)[i] = f2tf(Wo1[i]);
    }
}

// h init (+tf shadow), x copy, cupd zero, edge geometry (from input x)
__global__ void setupB_k(const int* __restrict__ types, const float* __restrict__ x,
                         const int* __restrict__ bonds)
{
    const long N1 = (long)BB * NN * HH;
    const long N2 = N1 + BB * NN * 3;
    const long N3 = N2 + BB * NN * 3;
    const long N4 = N3 + BB * EE;
    const long stride = (long)gridDim.x * 256;
    for (long idx = (long)blockIdx.x * 256 + threadIdx.x; idx < N4; idx += stride) {
        if (idx < N1) {
            int j = (int)(idx & 127);
            long bn = idx >> 7;
            int n = (int)(bn % NN), b = (int)(bn / NN);
            float v = g_table4[types[n] * HH + j] + g_temb[b * HH + j];
            g_h[idx] = v;
            ((uint32_t*)g_htf)[idx] = f2tf(v);
        } else if (idx < N2) {
            long i = idx - N1;
            g_x[i] = x[i];
        } else if (idx < N3) {
            g_cupd[idx - N2] = 0.f;
        } else {
            long i = idx - N3;
            int b = (int)(i / EE), e = (int)(i - (long)b * EE);
            int s = bonds[2 * e], d = bonds[2 * e + 1];
            const float* xs = x + ((long)b * NN + s) * 3;
            const float* xd = x + ((long)b * NN + d) * 3;
            float dx = xd[0] - xs[0], dy = xd[1] - xs[1], dz = xd[2] - xs[2];
            float dist = sqrtf(dx * dx + dy * dy + dz * dz);
            g_dist[i] = dist;
            float inv = 1.f / (dist + 1e-8f);
            g_cdn[i * 3 + 0] = dx * inv;
            g_cdn[i * 3 + 1] = dy * inv;
            g_cdn[i * 3 + 2] = dz * inv;
        }
    }
}

// per-layer (l>=1): cupd zero + edge geometry from g_x
__global__ void prep_k(const int* __restrict__ bonds)
{
    const long N1 = (long)BB * NN * 3;
    const long N2 = N1 + BB * EE;
    const long stride = (long)gridDim.x * 256;
    for (long idx = (long)blockIdx.x * 256 + threadIdx.x; idx < N2; idx += stride) {
        if (idx < N1) {
            g_cupd[idx] = 0.f;
        } else {
            long i = idx - N1;
            int b = (int)(i / EE), e = (int)(i - (long)b * EE);
            int s = bonds[2 * e], d = bonds[2 * e + 1];
            const float* xs = g_x + ((long)b * NN + s) * 3;
            const float* xd = g_x + ((long)b * NN + d) * 3;
            float dx = xd[0] - xs[0], dy = xd[1] - xs[1], dz = xd[2] - xs[2];
            float dist = sqrtf(dx * dx + dy * dy + dz * dz);
            g_dist[i] = dist;
            float inv = 1.f / (dist + 1e-8f);
            g_cdn[i * 3 + 0] = dx * inv;
            g_cdn[i * 3 + 1] = dy * inv;
            g_cdn[i * 3 + 2] = dz * inv;
        }
    }
}

// ---------------- CSR + scatter/gather kernels ------------------------------
__global__ void zero_i_k(int* __restrict__ p, int n)
{
    int idx = blockIdx.x * 256 + threadIdx.x;
    if (idx < n) p[idx] = 0;
}
__global__ void deg_count_k(const int* __restrict__ bonds)
{
    int e = blockIdx.x * 256 + threadIdx.x;
    if (e >= EE) return;
    atomicAdd(&g_deg[bonds[2 * e]], 1);
    atomicAdd(&g_deg[bonds[2 * e + 1]], 1);
}
__global__ void scan_k()
{
    __shared__ int sh[256];
    __shared__ int base;
    int tid = threadIdx.x;
    if (tid == 0) base = 0;
    __syncthreads();
    for (int i0 = 0; i0 < NN; i0 += 256) {
        int i = i0 + tid;
        int v = (i < NN) ? g_deg[i] : 0;
        sh[tid] = v;
        __syncthreads();
        for (int o = 1; o < 256; o <<= 1) {
            int t = (tid >= o) ? sh[tid - o] : 0;
            __syncthreads();
            sh[tid] += t;
            __syncthreads();
        }
        int excl = base + sh[tid] - v;
        if (i < NN) { g_off[i] = excl; g_cur[i] = excl; }
        __syncthreads();
        if (tid == 255) base += sh[255];
        __syncthreads();
    }
    if (tid == 0) g_off[NN] = base;
}
__global__ void fill_k(const int* __restrict__ bonds)
{
    int e = blockIdx.x * 256 + threadIdx.x;
    if (e >= EE) return;
    int s = bonds[2 * e], d = bonds[2 * e + 1];
    int p = atomicAdd(&g_cur[s], 1); g_csr[p] = e;
    int q = atomicAdd(&g_cur[d], 1); g_csr[q] = e;
}

// agg[b,n,:] = sum of m over incident edges (CSR gather), tf32-rounded store
__global__ void agg_gather_k()
{
    int warp = (blockIdx.x * 256 + threadIdx.x) >> 5;
    int lane = threadIdx.x & 31;
    if (warp >= BB * NN) return;
    int b = warp / NN, n = warp - b * NN;
    int o0 = g_off[n], o1 = g_off[n + 1];
    float4 acc = make_float4(0.f, 0.f, 0.f, 0.f);
    for (int j = o0; j < o1; j++) {
        int e = g_csr[j];
        float4 v = ((const float4*)(g_m + ((long)b * EE + e) * HH))[lane];
        acc.x += v.x; acc.y += v.y; acc.z += v.z; acc.w += v.w;
    }
    uint4 tf;
    tf.x = f2tf(acc.x); tf.y = f2tf(acc.y); tf.z = f2tf(acc.z); tf.w = f2tf(acc.w);
    ((uint4*)(g_agg + (long)warp * HH))[lane] = tf;
}

__global__ void x_update_k()
{
    int idx = blockIdx.x * 256 + threadIdx.x;
    if (idx >= BB * NN * 3) return;
    int n = (idx / 3) % NN;
    g_x[idx] += g_cupd[idx] / fmaxf((float)g_deg[n], 1.f);
}

// ---------------- launch ---------------------------------------------------
static inline int cdiv(long n, int b) { return (int)((n + b - 1) / b); }

extern "C" void kernel_launch(void* const* d_in, const int* in_sizes, int n_in,
                              void* d_out, int out_size)
{
    const float* x      = (const float*)d_in[0];
    const float* t      = (const float*)d_in[1];
    const int*   types  = (const int*)d_in[2];
    const int*   bonds  = (const int*)d_in[3];
    const float* emb    = (const float*)d_in[4];
    const float* W_t1   = (const float*)d_in[5];
    const float* b_t1   = (const float*)d_in[6];
    const float* W_t2   = (const float*)d_in[7];
    const float* b_t2   = (const float*)d_in[8];
    const float* W_node = (const float*)d_in[9];
    const float* b_node = (const float*)d_in[10];
    const float* Wm1    = (const float*)d_in[11];
    const float* bm1    = (const float*)d_in[12];
    const float* Wm2    = (const float*)d_in[13];
    const float* bm2    = (const float*)d_in[14];
    const float* Wn1    = (const float*)d_in[15];
    const float* bn1    = (const float*)d_in[16];
    const float* Wn2    = (const float*)d_in[17];
    const float* bn2    = (const float*)d_in[18];
    const float* Wc1    = (const float*)d_in[19];
    const float* bc1    = (const float*)d_in[20];
    const float* Wc2    = (const float*)d_in[21];
    const float* Wo1    = (const float*)d_in[22];
    const float* bo1    = (const float*)d_in[23];
    const float* Wo2    = (const float*)d_in[24];
    const float* bo2    = (const float*)d_in[25];
    float* out = (float*)d_out;

    float *p_wm1, *p_wm2, *p_wc1, *p_wn1, *p_wn2, *p_wo1;
    int *p_deg;
    cudaGetSymbolAddress((void**)&p_wm1, g_wm1);
    cudaGetSymbolAddress((void**)&p_wm2, g_wm2);
    cudaGetSymbolAddress((void**)&p_wc1, g_wc1);
    cudaGetSymbolAddress((void**)&p_wn1, g_wn1);
    cudaGetSymbolAddress((void**)&p_wn2, g_wn2);
    cudaGetSymbolAddress((void**)&p_wo1, g_wo1);
    cudaGetSymbolAddress((void**)&p_deg, g_deg);

    cudaFuncSetAttribute(edge_fused_k, cudaFuncAttributeMaxDynamicSharedMemorySize, FUSE_SMEM);
    cudaFuncSetAttribute(node_fused_k, cudaFuncAttributeMaxDynamicSharedMemorySize, FUSE_SMEM);
    cudaFuncSetAttribute(out_fused_k, cudaFuncAttributeMaxDynamicSharedMemorySize, FUSE_SMEM);

    const int gridE = BB * EE / 128;  // 2500
    const int gridN = BB * NN / 128;  // 1250

    setupA_k<<<194, 256>>>(t, W_t1, b_t1, W_t2, b_t2, emb, W_node, b_node,
                           Wm1, Wm2, Wc1, Wn1, Wn2, Wo1);
    setupB_k<<<4096, 256>>>(types, x, bonds);
    zero_i_k<<<cdiv(NN, 256), 256>>>(p_deg, NN);

    for (int l = 0; l < LL; l++) {
        if (l > 0) prep_k<<<2048, 256>>>(bonds);

        edge_fused_k<<<gridE, 256, FUSE_SMEM>>>(
            p_wm1 + (long)l * 257 * 128, bm1 + l * 128,
            Wm1 + ((long)l * 257 + 256) * 128,
            p_wm2 + (long)l * 16384, bm2 + l * 128,
            p_wc1 + (long)l * 16384, bc1 + l * 128, Wc2 + l * 128, bonds);

        if (l == 0) {
            deg_count_k<<<cdiv(EE, 256), 256>>>(bonds);
            scan_k<<<1, 256>>>();
            fill_k<<<cdiv(EE, 256), 256>>>(bonds);
        }

        agg_gather_k<<<cdiv((long)BB * NN * 32, 256), 256>>>();

        node_fused_k<<<gridN, 256, FUSE_SMEM>>>(
            p_wn1 + (long)l * 256 * 128, bn1 + l * 128,
            p_wn2 + (long)l * 16384, bn2 + l * 128);

        x_update_k<<<cdiv((long)BB * NN * 3, 256), 256>>>();
    }

    out_fused_k<<<gridN, 256, FUSE_SMEM>>>(p_wo1, bo1, Wo2, bo2, x, out);
}